// round 7
// baseline (speedup 1.0000x reference)
#include <cuda_runtime.h>
#include <math.h>

#define N_GENES 15135
#define BS 8
#define HID 64
#define NCMT 1000
#define HFC 128
#define NROWS (N_GENES * BS)       // 121080
#define FPN (BS * HID)             // 512 floats per node
#define E_MAX 262144
#define P_MAX 131072

// ------------------- scratch (static device globals; no runtime alloc) -----
__device__ float g_bufA[(size_t)N_GENES * FPN];   // 31 MB
__device__ float g_bufB[(size_t)N_GENES * FPN];   // 31 MB
__device__ float g_dinv[N_GENES];
__device__ int   g_fill[N_GENES];
__device__ int   g_rowptr[N_GENES + 1];
__device__ int   g_csr_src [E_MAX];
__device__ float g_csr_norm[E_MAX];
// pathway CSR (segments = communities/cols)
__device__ int   g_fill2[NCMT];
__device__ int   g_rowptr2[NCMT + 1];
__device__ int   g_csr2_row[P_MAX];
__device__ float g_s[(size_t)NROWS];      // s[n*8+b], accumulated across 3 layers
__device__ float g_pool[NCMT * BS];       // pooled mean + fcb, [c*8+b]
__device__ double g_part[8 * BS * HFC];   // mlp1 partials [chunk][b][j]

// ------------------- fused setup: degrees + scans + fill-resets -------------
__global__ void scans_fused_kernel(const int* __restrict__ ei, int E,
                                   const int* __restrict__ pcol, int P) {
    extern __shared__ int hist[];
    __shared__ int sh[1024];
    int tid = threadIdx.x;
    if (blockIdx.x == 0) {
        for (int i = tid; i < N_GENES; i += 1024) { hist[i] = 0; g_fill[i] = 0; }
        __syncthreads();
        for (int e = tid; e < E; e += 1024) atomicAdd(&hist[ei[E + e]], 1);
        __syncthreads();
        int carry = 0;
        for (int base = 0; base < N_GENES; base += 1024) {
            int i = base + tid;
            int v = (i < N_GENES) ? hist[i] : 0;
            if (i < N_GENES) g_dinv[i] = 1.0f / sqrtf((float)v + 1.0f);
            sh[tid] = v;
            __syncthreads();
            for (int off = 1; off < 1024; off <<= 1) {
                int t = (tid >= off) ? sh[tid - off] : 0;
                __syncthreads();
                sh[tid] += t;
                __syncthreads();
            }
            if (i < N_GENES) g_rowptr[i] = carry + sh[tid] - v;  // exclusive
            carry += sh[1023];
            __syncthreads();
        }
        if (tid == 0) g_rowptr[N_GENES] = carry;
    } else {
        for (int i = tid; i < NCMT; i += 1024) { hist[i] = 0; g_fill2[i] = 0; }
        __syncthreads();
        for (int p = tid; p < P; p += 1024) atomicAdd(&hist[pcol[p]], 1);
        __syncthreads();
        int v = (tid < NCMT) ? hist[tid] : 0;
        sh[tid] = v;
        __syncthreads();
        for (int off = 1; off < 1024; off <<= 1) {
            int t = (tid >= off) ? sh[tid - off] : 0;
            __syncthreads();
            sh[tid] += t;
            __syncthreads();
        }
        if (tid < NCMT) g_rowptr2[tid] = sh[tid] - v;
        if (tid == NCMT - 1) g_rowptr2[NCMT] = sh[tid];
    }
}

// fused CSR fills
__global__ void fills_kernel(const int* __restrict__ ei, int E,
                             const int* __restrict__ prow,
                             const int* __restrict__ pcol, int P) {
    int i = blockIdx.x * blockDim.x + threadIdx.x;
    if (i < E) {
        int src = ei[i];
        int dst = ei[E + i];
        int pos = g_rowptr[dst] + atomicAdd(&g_fill[dst], 1);
        g_csr_src[pos] = src;
        g_csr_norm[pos] = g_dinv[src] * g_dinv[dst];
    }
    if (i < P) {
        int c = pcol[i];
        int pos = g_rowptr2[c] + atomicAdd(&g_fill2[c], 1);
        g_csr2_row[pos] = prow[i];
    }
}

// ------------------- GEMM: out[r*64+f] = sum_k in_row(r)[k] * W[k*64+f] ----
// 64 rows x 64 cols per block, 256 threads, 4x4 register tile per thread.
// layout==0: input is x [bs, N, 64], row r -> (n=r>>3, b=r&7)
// layout==1: input is [N, bs, 64] flat, row r contiguous
#define A_PAD 68
__global__ void __launch_bounds__(256) gemm_kernel(
        const float* __restrict__ in, const float* __restrict__ W,
        float* __restrict__ out, int layout) {
    __shared__ float sA[64][A_PAD];   // row-major rows of input
    __shared__ float sW[64][64];      // W[k][f], row-major (as in gmem)
    int tid = threadIdx.x;
    int rbase = blockIdx.x * 64;

    // load W: 1024 float4
    for (int i = tid; i < 1024; i += 256) {
        int k = i >> 4, f4 = i & 15;
        ((float4*)&sW[k][0])[f4] = ((const float4*)W)[i];
    }
    // load A: 64 rows x 16 float4
    for (int i = tid; i < 1024; i += 256) {
        int rr = i >> 4, c4 = i & 15;
        int grow = rbase + rr;
        float4 v = make_float4(0.f, 0.f, 0.f, 0.f);
        if (grow < NROWS) {
            const float* src;
            if (layout == 0) {
                int nn = grow >> 3, bb = grow & 7;
                src = in + ((size_t)bb * N_GENES + nn) * 64;
            } else {
                src = in + (size_t)grow * 64;
            }
            v = ((const float4*)src)[c4];
        }
        ((float4*)&sA[rr][0])[c4] = v;
    }
    __syncthreads();

    int tx = tid & 15;          // col group: cols tx*4 .. tx*4+3
    int ty = tid >> 4;          // row group: rows ty*4 .. ty*4+3
    float acc[4][4];
#pragma unroll
    for (int i = 0; i < 4; i++)
#pragma unroll
        for (int j = 0; j < 4; j++) acc[i][j] = 0.f;

#pragma unroll 4
    for (int k = 0; k < 64; k++) {
        float4 b = *(const float4*)&sW[k][tx * 4];
        float a0 = sA[ty * 4 + 0][k];
        float a1 = sA[ty * 4 + 1][k];
        float a2 = sA[ty * 4 + 2][k];
        float a3 = sA[ty * 4 + 3][k];
        acc[0][0] += a0 * b.x; acc[0][1] += a0 * b.y; acc[0][2] += a0 * b.z; acc[0][3] += a0 * b.w;
        acc[1][0] += a1 * b.x; acc[1][1] += a1 * b.y; acc[1][2] += a1 * b.z; acc[1][3] += a1 * b.w;
        acc[2][0] += a2 * b.x; acc[2][1] += a2 * b.y; acc[2][2] += a2 * b.z; acc[2][3] += a2 * b.w;
        acc[3][0] += a3 * b.x; acc[3][1] += a3 * b.y; acc[3][2] += a3 * b.z; acc[3][3] += a3 * b.w;
    }
#pragma unroll
    for (int i = 0; i < 4; i++) {
        int grow = rbase + ty * 4 + i;
        if (grow < NROWS) {
            float4 o = make_float4(acc[i][0], acc[i][1], acc[i][2], acc[i][3]);
            ((float4*)&out[(size_t)grow * 64])[tx] = o;
        }
    }
}

// ------------------- GCN aggregate + fc-dot contribution ---------------------
// x = relu(sum_e w*h[src] + dinv^2*h[n] + b); optionally store x (xout!=0);
// accumulates s[n,b] (+)= sum_h x[b,h] * fcW[3h + fc_off]
__global__ void __launch_bounds__(128) agg_s_kernel(
        const float* __restrict__ h, const float* __restrict__ b,
        float* __restrict__ xout, const float* __restrict__ fcW,
        int fc_off, int accum) {
    int n = blockIdx.x;
    int t = threadIdx.x;                          // 0..127, float4 lanes
    const float4* __restrict__ h4 = (const float4*)h;
    float dv = g_dinv[n];
    float4 acc = h4[(size_t)n * 128 + t];
    float w0 = dv * dv;
    acc.x *= w0; acc.y *= w0; acc.z *= w0; acc.w *= w0;
    float4 acc2 = make_float4(0.f, 0.f, 0.f, 0.f);
    int e0 = g_rowptr[n], e1 = g_rowptr[n + 1];
    int e = e0;
    for (; e + 8 <= e1; e += 8) {
        int   s0 = g_csr_src[e],     s1 = g_csr_src[e + 1];
        int   s2 = g_csr_src[e + 2], s3 = g_csr_src[e + 3];
        int   s4 = g_csr_src[e + 4], s5 = g_csr_src[e + 5];
        int   s6 = g_csr_src[e + 6], s7 = g_csr_src[e + 7];
        float u0 = g_csr_norm[e],     u1 = g_csr_norm[e + 1];
        float u2 = g_csr_norm[e + 2], u3 = g_csr_norm[e + 3];
        float u4 = g_csr_norm[e + 4], u5 = g_csr_norm[e + 5];
        float u6 = g_csr_norm[e + 6], u7 = g_csr_norm[e + 7];
        float4 v0 = h4[(size_t)s0 * 128 + t];
        float4 v1 = h4[(size_t)s1 * 128 + t];
        float4 v2 = h4[(size_t)s2 * 128 + t];
        float4 v3 = h4[(size_t)s3 * 128 + t];
        float4 v4 = h4[(size_t)s4 * 128 + t];
        float4 v5 = h4[(size_t)s5 * 128 + t];
        float4 v6 = h4[(size_t)s6 * 128 + t];
        float4 v7 = h4[(size_t)s7 * 128 + t];
        acc.x  += u0 * v0.x; acc.y  += u0 * v0.y; acc.z  += u0 * v0.z; acc.w  += u0 * v0.w;
        acc2.x += u1 * v1.x; acc2.y += u1 * v1.y; acc2.z += u1 * v1.z; acc2.w += u1 * v1.w;
        acc.x  += u2 * v2.x; acc.y  += u2 * v2.y; acc.z  += u2 * v2.z; acc.w  += u2 * v2.w;
        acc2.x += u3 * v3.x; acc2.y += u3 * v3.y; acc2.z += u3 * v3.z; acc2.w += u3 * v3.w;
        acc.x  += u4 * v4.x; acc.y  += u4 * v4.y; acc.z  += u4 * v4.z; acc.w  += u4 * v4.w;
        acc2.x += u5 * v5.x; acc2.y += u5 * v5.y; acc2.z += u5 * v5.z; acc2.w += u5 * v5.w;
        acc.x  += u6 * v6.x; acc.y  += u6 * v6.y; acc.z  += u6 * v6.z; acc.w  += u6 * v6.w;
        acc2.x += u7 * v7.x; acc2.y += u7 * v7.y; acc2.z += u7 * v7.z; acc2.w += u7 * v7.w;
    }
    for (; e < e1; e++) {
        int s = g_csr_src[e];
        float w = g_csr_norm[e];
        float4 v = h4[(size_t)s * 128 + t];
        acc.x += w * v.x; acc.y += w * v.y; acc.z += w * v.z; acc.w += w * v.w;
    }
    acc.x += acc2.x; acc.y += acc2.y; acc.z += acc2.z; acc.w += acc2.w;
    float4 bb = ((const float4*)b)[t & 15];
    acc.x = fmaxf(acc.x + bb.x, 0.f);
    acc.y = fmaxf(acc.y + bb.y, 0.f);
    acc.z = fmaxf(acc.z + bb.z, 0.f);
    acc.w = fmaxf(acc.w + bb.w, 0.f);
    if (xout) ((float4*)xout)[(size_t)n * 128 + t] = acc;

    // fc-dot contribution: s_part over this thread's 4 hid components
    int ht = (t & 15) * 4;
    float sp = acc.x * fcW[3 * ht + fc_off]
             + acc.y * fcW[3 * (ht + 1) + fc_off]
             + acc.z * fcW[3 * (ht + 2) + fc_off]
             + acc.w * fcW[3 * (ht + 3) + fc_off];
#pragma unroll
    for (int off = 8; off; off >>= 1) sp += __shfl_xor_sync(0xffffffffu, sp, off);
    if ((t & 15) == 0) {
        int bidx = t >> 4;
        size_t idx = (size_t)n * 8 + bidx;
        g_s[idx] = accum ? (g_s[idx] + sp) : sp;
    }
}

// ------------------- pathway pooled mean via CSR (deterministic, double) ----
__global__ void __launch_bounds__(256) pool_kernel(const float* __restrict__ fcb) {
    __shared__ double sh[256];
    int c = blockIdx.x;
    int tid = threadIdx.x;
    int b = tid & 7;          // batch lane
    int i = tid >> 3;         // entry lane 0..31
    int e0 = g_rowptr2[c], e1 = g_rowptr2[c + 1];
    double acc = 0.0;
    for (int e = e0 + i; e < e1; e += 32) {
        int r = g_csr2_row[e];
        acc += (double)g_s[(size_t)r * 8 + b];
    }
    sh[tid] = acc;
    __syncthreads();
    for (int off = 128; off >= 8; off >>= 1) {
        if (tid < off) sh[tid] += sh[tid + off];
        __syncthreads();
    }
    if (tid < 8) {
        double cnt = (double)(e1 - e0);
        if (cnt < 1.0) cnt = 1.0;
        g_pool[c * 8 + tid] = (float)(sh[tid] / cnt + (double)fcb[0]);
    }
}

// ------------------- MLP head (double accumulation, parallel chunks) --------
__global__ void __launch_bounds__(128) mlp1_kernel(const float* __restrict__ l1W) {
    int b = blockIdx.x & 7;
    int chunk = blockIdx.x >> 3;
    int j = threadIdx.x;
    int c0 = chunk * 125, c1 = c0 + 125;
    double acc = 0.0;
    for (int c = c0; c < c1; c++)
        acc += (double)g_pool[c * 8 + b] * (double)l1W[c * HFC + j];
    g_part[((size_t)chunk * 8 + b) * HFC + j] = acc;
}

__global__ void __launch_bounds__(128) mlp2_kernel(
        const float* __restrict__ l1b, const float* __restrict__ l2W,
        const float* __restrict__ l2b, float* __restrict__ out) {
    __shared__ double sz0[128], sz1[128];
    int b = blockIdx.x, j = threadIdx.x;
    double hv = (double)l1b[j];
#pragma unroll
    for (int k = 0; k < 8; k++) hv += g_part[((size_t)k * 8 + b) * HFC + j];
    if (hv < 0.0) hv = 0.0;
    sz0[j] = hv * (double)l2W[j * 2];
    sz1[j] = hv * (double)l2W[j * 2 + 1];
    __syncthreads();
    for (int off = 64; off; off >>= 1) {
        if (j < off) { sz0[j] += sz0[j + off]; sz1[j] += sz1[j + off]; }
        __syncthreads();
    }
    if (j == 0) {
        double z0 = sz0[0] + (double)l2b[0];
        double z1 = sz1[0] + (double)l2b[1];
        double m = z0 > z1 ? z0 : z1;
        double lse = m + log(exp(z0 - m) + exp(z1 - m));
        out[b * 2]     = (float)(z0 - lse);
        out[b * 2 + 1] = (float)(z1 - lse);
    }
}

// ------------------- launch --------------------------------------------------
extern "C" void kernel_launch(void* const* d_in, const int* in_sizes, int n_in,
                              void* d_out, int out_size) {
    const float* x    = (const float*)d_in[0];
    const int*   ei   = (const int*)  d_in[2];
    const int*   prow = (const int*)  d_in[3];
    const int*   pcol = (const int*)  d_in[4];
    const float* W1   = (const float*)d_in[5];
    const float* b1   = (const float*)d_in[6];
    const float* W2   = (const float*)d_in[7];
    const float* b2   = (const float*)d_in[8];
    const float* W3   = (const float*)d_in[9];
    const float* b3   = (const float*)d_in[10];
    const float* fcW  = (const float*)d_in[11];
    const float* fcb  = (const float*)d_in[12];
    const float* l1W  = (const float*)d_in[13];
    const float* l1b  = (const float*)d_in[14];
    const float* l2W  = (const float*)d_in[15];
    const float* l2b  = (const float*)d_in[16];
    float* out = (float*)d_out;

    int E = in_sizes[2] / 2;
    int P = in_sizes[3];
    int EP = E > P ? E : P;

    int gemm_blocks = (NROWS + 63) / 64;                      // 1892
    const int smem_hist = (N_GENES + 1) * (int)sizeof(int);   // ~60.5 KB
    cudaFuncSetAttribute(scans_fused_kernel,
                         cudaFuncAttributeMaxDynamicSharedMemorySize, smem_hist);

    float* A = g_bufA;
    float* B = g_bufB;

    // launch index (ncu captures my launch idx 3):
    gemm_kernel<<<gemm_blocks, 256>>>(x, W1, A, 0);                        // 0
    scans_fused_kernel<<<2, 1024, smem_hist>>>(ei, E, pcol, P);            // 1
    fills_kernel<<<(EP + 255) / 256, 256>>>(ei, E, prow, pcol, P);         // 2
    agg_s_kernel<<<N_GENES, 128>>>(A, b1, B, fcW, 0, 0);                   // 3 <- profiled
    gemm_kernel<<<gemm_blocks, 256>>>(B, W2, A, 1);                        // 4
    agg_s_kernel<<<N_GENES, 128>>>(A, b2, B, fcW, 1, 1);                   // 5
    gemm_kernel<<<gemm_blocks, 256>>>(B, W3, A, 1);                        // 6
    agg_s_kernel<<<N_GENES, 128>>>(A, b3, (float*)0, fcW, 2, 1);           // 7
    pool_kernel<<<NCMT, 256>>>(fcb);                                       // 8
    mlp1_kernel<<<64, HFC>>>(l1W);                                         // 9
    mlp2_kernel<<<BS, HFC>>>(l1b, l2W, l2b, out);                          // 10
}

// round 8
// speedup vs baseline: 1.0567x; 1.0567x over previous
#include <cuda_runtime.h>
#include <math.h>

#define N_GENES 15135
#define BS 8
#define HID 64
#define NCMT 1000
#define HFC 128
#define NROWS (N_GENES * BS)       // 121080
#define FPN (BS * HID)             // 512 floats per node
#define E_MAX 262144
#define P_MAX 131072

// ------------------- scratch (static device globals; no runtime alloc) -----
__device__ float g_bufA[(size_t)N_GENES * FPN];   // 31 MB
__device__ float g_bufB[(size_t)N_GENES * FPN];   // 31 MB
__device__ float g_dinv[N_GENES];
__device__ int   g_fill[N_GENES];
__device__ int   g_rowptr[N_GENES + 1];
__device__ int   g_csr_src [E_MAX];
__device__ float g_csr_norm[E_MAX];
// pathway CSR (segments = communities/cols)
__device__ int   g_fill2[NCMT];
__device__ int   g_rowptr2[NCMT + 1];
__device__ int   g_csr2_row[P_MAX];
__device__ float g_s[(size_t)NROWS];      // s[n*8+b], accumulated across 3 layers
__device__ float g_pool[NCMT * BS];       // pooled mean + fcb, [c*8+b]
__device__ double g_part[8 * BS * HFC];   // mlp1 partials [chunk][b][j]

// ------------------- fused setup: degrees + scans + fill-resets -------------
__global__ void scans_fused_kernel(const int* __restrict__ ei, int E,
                                   const int* __restrict__ pcol, int P) {
    extern __shared__ int hist[];
    __shared__ int sh[1024];
    int tid = threadIdx.x;
    if (blockIdx.x == 0) {
        for (int i = tid; i < N_GENES; i += 1024) { hist[i] = 0; g_fill[i] = 0; }
        __syncthreads();
        for (int e = tid; e < E; e += 1024) atomicAdd(&hist[ei[E + e]], 1);
        __syncthreads();
        int carry = 0;
        for (int base = 0; base < N_GENES; base += 1024) {
            int i = base + tid;
            int v = (i < N_GENES) ? hist[i] : 0;
            if (i < N_GENES) g_dinv[i] = 1.0f / sqrtf((float)v + 1.0f);
            sh[tid] = v;
            __syncthreads();
            for (int off = 1; off < 1024; off <<= 1) {
                int t = (tid >= off) ? sh[tid - off] : 0;
                __syncthreads();
                sh[tid] += t;
                __syncthreads();
            }
            if (i < N_GENES) g_rowptr[i] = carry + sh[tid] - v;  // exclusive
            carry += sh[1023];
            __syncthreads();
        }
        if (tid == 0) g_rowptr[N_GENES] = carry;
    } else {
        for (int i = tid; i < NCMT; i += 1024) { hist[i] = 0; g_fill2[i] = 0; }
        __syncthreads();
        for (int p = tid; p < P; p += 1024) atomicAdd(&hist[pcol[p]], 1);
        __syncthreads();
        int v = (tid < NCMT) ? hist[tid] : 0;
        sh[tid] = v;
        __syncthreads();
        for (int off = 1; off < 1024; off <<= 1) {
            int t = (tid >= off) ? sh[tid - off] : 0;
            __syncthreads();
            sh[tid] += t;
            __syncthreads();
        }
        if (tid < NCMT) g_rowptr2[tid] = sh[tid] - v;
        if (tid == NCMT - 1) g_rowptr2[NCMT] = sh[tid];
    }
}

// fused CSR fills
__global__ void fills_kernel(const int* __restrict__ ei, int E,
                             const int* __restrict__ prow,
                             const int* __restrict__ pcol, int P) {
    int i = blockIdx.x * blockDim.x + threadIdx.x;
    if (i < E) {
        int src = ei[i];
        int dst = ei[E + i];
        int pos = g_rowptr[dst] + atomicAdd(&g_fill[dst], 1);
        g_csr_src[pos] = src;
        g_csr_norm[pos] = g_dinv[src] * g_dinv[dst];
    }
    if (i < P) {
        int c = pcol[i];
        int pos = g_rowptr2[c] + atomicAdd(&g_fill2[c], 1);
        g_csr2_row[pos] = prow[i];
    }
}

// ------------------- GEMM1: out[r*64+f] = sum_k x_row(r)[k] * W[k*64+f] ----
// input x [bs, N, 64], row r -> (n=r>>3, b=r&7); out [N][bs][64] flat.
#define A_PAD 68
__global__ void __launch_bounds__(256) gemm_kernel(
        const float* __restrict__ in, const float* __restrict__ W,
        float* __restrict__ out) {
    __shared__ float sA[64][A_PAD];
    __shared__ float sW[64][64];
    int tid = threadIdx.x;
    int rbase = blockIdx.x * 64;
    for (int i = tid; i < 1024; i += 256) {
        int k = i >> 4, f4 = i & 15;
        ((float4*)&sW[k][0])[f4] = ((const float4*)W)[i];
    }
    for (int i = tid; i < 1024; i += 256) {
        int rr = i >> 4, c4 = i & 15;
        int grow = rbase + rr;
        float4 v = make_float4(0.f, 0.f, 0.f, 0.f);
        if (grow < NROWS) {
            int nn = grow >> 3, bb = grow & 7;
            v = ((const float4*)(in + ((size_t)bb * N_GENES + nn) * 64))[c4];
        }
        ((float4*)&sA[rr][0])[c4] = v;
    }
    __syncthreads();
    int tx = tid & 15, ty = tid >> 4;
    float acc[4][4];
#pragma unroll
    for (int i = 0; i < 4; i++)
#pragma unroll
        for (int j = 0; j < 4; j++) acc[i][j] = 0.f;
#pragma unroll 4
    for (int k = 0; k < 64; k++) {
        float4 b = *(const float4*)&sW[k][tx * 4];
        float a0 = sA[ty * 4 + 0][k];
        float a1 = sA[ty * 4 + 1][k];
        float a2 = sA[ty * 4 + 2][k];
        float a3 = sA[ty * 4 + 3][k];
        acc[0][0] += a0 * b.x; acc[0][1] += a0 * b.y; acc[0][2] += a0 * b.z; acc[0][3] += a0 * b.w;
        acc[1][0] += a1 * b.x; acc[1][1] += a1 * b.y; acc[1][2] += a1 * b.z; acc[1][3] += a1 * b.w;
        acc[2][0] += a2 * b.x; acc[2][1] += a2 * b.y; acc[2][2] += a2 * b.z; acc[2][3] += a2 * b.w;
        acc[3][0] += a3 * b.x; acc[3][1] += a3 * b.y; acc[3][2] += a3 * b.z; acc[3][3] += a3 * b.w;
    }
#pragma unroll
    for (int i = 0; i < 4; i++) {
        int grow = rbase + ty * 4 + i;
        if (grow < NROWS) {
            float4 o = make_float4(acc[i][0], acc[i][1], acc[i][2], acc[i][3]);
            ((float4*)&out[(size_t)grow * 64])[tx] = o;
        }
    }
}

// ------------------- fused GCN aggregate + fc-dot + next-layer GEMM ----------
// x = relu(sum_e w*h_in[src] + dinv^2*h_in[n] + bias)      (in registers)
// s[n,b] (+)= sum_h x[b,h] * fcW[3h+fc_off]
// if W_next: h_out[n] = x @ W_next                         (smem gemm)
// thread t in [0,128): b = t>>4, quad q = t&15 (hid dims 4q..4q+3)
__global__ void __launch_bounds__(128) agg_fused_kernel(
        const float* __restrict__ h_in, const float* __restrict__ bias,
        const float* __restrict__ W_next, float* __restrict__ h_out,
        const float* __restrict__ fcW, int fc_off, int accum) {
    __shared__ float sW[64 * 64];      // 16 KB (next-layer W)
    __shared__ float sX[512];          // 2 KB  (x tile, [b][64])
    __shared__ int   sSrc[128];
    __shared__ float sNrm[128];

    int n = blockIdx.x;
    int t = threadIdx.x;
    const float4* __restrict__ h4 = (const float4*)h_in;

    // preload next-layer W while gathering
    if (W_next) {
        for (int i = t; i < 1024; i += 128)
            ((float4*)sW)[i] = ((const float4*)W_next)[i];
    }

    float dv = g_dinv[n];
    float4 acc = h4[(size_t)n * 128 + t];
    float w0 = dv * dv;
    acc.x *= w0; acc.y *= w0; acc.z *= w0; acc.w *= w0;
    float4 acc2 = make_float4(0.f, 0.f, 0.f, 0.f);

    int e0 = g_rowptr[n], e1 = g_rowptr[n + 1];
    for (int cs = e0; cs < e1; cs += 128) {
        int idx = cs + t;
        if (idx < e1) { sSrc[t] = g_csr_src[idx]; sNrm[t] = g_csr_norm[idx]; }
        __syncthreads();
        int m = e1 - cs; if (m > 128) m = 128;
        int j = 0;
        for (; j + 4 <= m; j += 4) {
            int   s0 = sSrc[j],     s1 = sSrc[j + 1];
            int   s2 = sSrc[j + 2], s3 = sSrc[j + 3];
            float u0 = sNrm[j],     u1 = sNrm[j + 1];
            float u2 = sNrm[j + 2], u3 = sNrm[j + 3];
            float4 v0 = h4[(size_t)s0 * 128 + t];
            float4 v1 = h4[(size_t)s1 * 128 + t];
            float4 v2 = h4[(size_t)s2 * 128 + t];
            float4 v3 = h4[(size_t)s3 * 128 + t];
            acc.x  += u0 * v0.x; acc.y  += u0 * v0.y; acc.z  += u0 * v0.z; acc.w  += u0 * v0.w;
            acc2.x += u1 * v1.x; acc2.y += u1 * v1.y; acc2.z += u1 * v1.z; acc2.w += u1 * v1.w;
            acc.x  += u2 * v2.x; acc.y  += u2 * v2.y; acc.z  += u2 * v2.z; acc.w  += u2 * v2.w;
            acc2.x += u3 * v3.x; acc2.y += u3 * v3.y; acc2.z += u3 * v3.z; acc2.w += u3 * v3.w;
        }
        for (; j < m; j++) {
            int s = sSrc[j];
            float u = sNrm[j];
            float4 v = h4[(size_t)s * 128 + t];
            acc.x += u * v.x; acc.y += u * v.y; acc.z += u * v.z; acc.w += u * v.w;
        }
        __syncthreads();
    }
    acc.x += acc2.x; acc.y += acc2.y; acc.z += acc2.z; acc.w += acc2.w;
    float4 bb = ((const float4*)bias)[t & 15];
    acc.x = fmaxf(acc.x + bb.x, 0.f);
    acc.y = fmaxf(acc.y + bb.y, 0.f);
    acc.z = fmaxf(acc.z + bb.z, 0.f);
    acc.w = fmaxf(acc.w + bb.w, 0.f);

    // fc-dot contribution
    int ht = (t & 15) * 4;
    float sp = acc.x * fcW[3 * ht + fc_off]
             + acc.y * fcW[3 * (ht + 1) + fc_off]
             + acc.z * fcW[3 * (ht + 2) + fc_off]
             + acc.w * fcW[3 * (ht + 3) + fc_off];
#pragma unroll
    for (int off = 8; off; off >>= 1) sp += __shfl_xor_sync(0xffffffffu, sp, off);
    if ((t & 15) == 0) {
        size_t idx = (size_t)n * 8 + (t >> 4);
        g_s[idx] = accum ? (g_s[idx] + sp) : sp;
    }

    // next-layer gemm: h_out[n][b][f] = sum_k x[b][k] * W[k][f]
    if (W_next) {
        ((float4*)sX)[t] = acc;     // sX[b*64 + 4q .. +3]
        __syncthreads();
        int b = t >> 4, q = t & 15;
        const float* xrow = sX + b * 64;
        float4 o = make_float4(0.f, 0.f, 0.f, 0.f);
#pragma unroll 8
        for (int k = 0; k < 64; k++) {
            float a = xrow[k];
            float4 w = ((const float4*)(sW + k * 64))[q];
            o.x += a * w.x; o.y += a * w.y; o.z += a * w.z; o.w += a * w.w;
        }
        ((float4*)h_out)[(size_t)n * 128 + t] = o;
    }
}

// ------------------- pathway pooled mean via CSR (deterministic, double) ----
__global__ void __launch_bounds__(256) pool_kernel(const float* __restrict__ fcb) {
    __shared__ double sh[256];
    int c = blockIdx.x;
    int tid = threadIdx.x;
    int b = tid & 7;
    int i = tid >> 3;
    int e0 = g_rowptr2[c], e1 = g_rowptr2[c + 1];
    double acc = 0.0;
    for (int e = e0 + i; e < e1; e += 32) {
        int r = g_csr2_row[e];
        acc += (double)g_s[(size_t)r * 8 + b];
    }
    sh[tid] = acc;
    __syncthreads();
    for (int off = 128; off >= 8; off >>= 1) {
        if (tid < off) sh[tid] += sh[tid + off];
        __syncthreads();
    }
    if (tid < 8) {
        double cnt = (double)(e1 - e0);
        if (cnt < 1.0) cnt = 1.0;
        g_pool[c * 8 + tid] = (float)(sh[tid] / cnt + (double)fcb[0]);
    }
}

// ------------------- MLP head (double accumulation, parallel chunks) --------
__global__ void __launch_bounds__(128) mlp1_kernel(const float* __restrict__ l1W) {
    int b = blockIdx.x & 7;
    int chunk = blockIdx.x >> 3;
    int j = threadIdx.x;
    int c0 = chunk * 125, c1 = c0 + 125;
    double acc = 0.0;
    for (int c = c0; c < c1; c++)
        acc += (double)g_pool[c * 8 + b] * (double)l1W[c * HFC + j];
    g_part[((size_t)chunk * 8 + b) * HFC + j] = acc;
}

__global__ void __launch_bounds__(128) mlp2_kernel(
        const float* __restrict__ l1b, const float* __restrict__ l2W,
        const float* __restrict__ l2b, float* __restrict__ out) {
    __shared__ double sz0[128], sz1[128];
    int b = blockIdx.x, j = threadIdx.x;
    double hv = (double)l1b[j];
#pragma unroll
    for (int k = 0; k < 8; k++) hv += g_part[((size_t)k * 8 + b) * HFC + j];
    if (hv < 0.0) hv = 0.0;
    sz0[j] = hv * (double)l2W[j * 2];
    sz1[j] = hv * (double)l2W[j * 2 + 1];
    __syncthreads();
    for (int off = 64; off; off >>= 1) {
        if (j < off) { sz0[j] += sz0[j + off]; sz1[j] += sz1[j + off]; }
        __syncthreads();
    }
    if (j == 0) {
        double z0 = sz0[0] + (double)l2b[0];
        double z1 = sz1[0] + (double)l2b[1];
        double m = z0 > z1 ? z0 : z1;
        double lse = m + log(exp(z0 - m) + exp(z1 - m));
        out[b * 2]     = (float)(z0 - lse);
        out[b * 2 + 1] = (float)(z1 - lse);
    }
}

// ------------------- launch --------------------------------------------------
extern "C" void kernel_launch(void* const* d_in, const int* in_sizes, int n_in,
                              void* d_out, int out_size) {
    const float* x    = (const float*)d_in[0];
    const int*   ei   = (const int*)  d_in[2];
    const int*   prow = (const int*)  d_in[3];
    const int*   pcol = (const int*)  d_in[4];
    const float* W1   = (const float*)d_in[5];
    const float* b1   = (const float*)d_in[6];
    const float* W2   = (const float*)d_in[7];
    const float* b2   = (const float*)d_in[8];
    const float* W3   = (const float*)d_in[9];
    const float* b3   = (const float*)d_in[10];
    const float* fcW  = (const float*)d_in[11];
    const float* fcb  = (const float*)d_in[12];
    const float* l1W  = (const float*)d_in[13];
    const float* l1b  = (const float*)d_in[14];
    const float* l2W  = (const float*)d_in[15];
    const float* l2b  = (const float*)d_in[16];
    float* out = (float*)d_out;

    int E = in_sizes[2] / 2;
    int P = in_sizes[3];
    int EP = E > P ? E : P;

    int gemm_blocks = (NROWS + 63) / 64;                      // 1892
    const int smem_hist = (N_GENES + 1) * (int)sizeof(int);   // ~60.5 KB
    cudaFuncSetAttribute(scans_fused_kernel,
                         cudaFuncAttributeMaxDynamicSharedMemorySize, smem_hist);

    // launch index (ncu captures my launch idx 3):
    gemm_kernel<<<gemm_blocks, 256>>>(x, W1, g_bufA);                        // 0
    scans_fused_kernel<<<2, 1024, smem_hist>>>(ei, E, pcol, P);              // 1
    fills_kernel<<<(EP + 255) / 256, 256>>>(ei, E, prow, pcol, P);           // 2
    agg_fused_kernel<<<N_GENES, 128>>>(g_bufA, b1, W2, g_bufB, fcW, 0, 0);   // 3 <- profiled
    agg_fused_kernel<<<N_GENES, 128>>>(g_bufB, b2, W3, g_bufA, fcW, 1, 1);   // 4
    agg_fused_kernel<<<N_GENES, 128>>>(g_bufA, b3, (const float*)0,
                                       (float*)0, fcW, 2, 1);                // 5
    pool_kernel<<<NCMT, 256>>>(fcb);                                         // 6
    mlp1_kernel<<<64, HFC>>>(l1W);                                           // 7
    mlp2_kernel<<<BS, HFC>>>(l1b, l2W, l2b, out);                            // 8
}